// round 1
// baseline (speedup 1.0000x reference)
#include <cuda_runtime.h>
#include <cmath>

// Fully-fused Swin block: shifted-window attention + LayerNorm + MLP + residual.
// One thread block per 7x7 window (8192 blocks), 256 threads (8 warps),
// each warp owns 7 token rows (rows 49..55 are zero padding).
// SMEM buffers are recycled across phases:
//   sX : input tile          -> attention output (AO)
//   sQ : Q (pre-scaled)      -> proj output (xr, residual)
//   sK : K                   -> LayerNorm output
//   sV : V                   -> gelu(fc1) hidden tile (per 96-wide chunk)

namespace {

constexpr int WSZ   = 7;
constexpr int NTOK  = 49;
constexpr int NPAD  = 56;
constexpr int CDIM  = 96;
constexpr int NHEAD = 3;
constexpr int HDIM  = 32;
constexpr int IMG   = 224;
constexpr int PITCH = 98;     // row pitch (98%32==2 -> at most 2-way conflicts on K rows)
constexpr int SHIFT_SZ = 3;
constexpr int HID   = 384;
constexpr int ROW   = NPAD * PITCH;             // 5488 floats per buffer
constexpr int SMEM_FLOATS = 4 * ROW + 512;      // 4 tiles + rpb table
constexpr int SMEM_BYTES  = SMEM_FLOATS * 4;    // 89856 B -> 2 blocks/SM

__global__ void __launch_bounds__(256, 2) swin_fused(
    const float* __restrict__ x,
    const float* __restrict__ qkv_w,
    const float* __restrict__ qkv_b,
    const float* __restrict__ proj_w,
    const float* __restrict__ proj_b,
    const float* __restrict__ rpb,
    const float* __restrict__ n2g,
    const float* __restrict__ n2b,
    const float* __restrict__ fc1_w,
    const float* __restrict__ fc1_b,
    const float* __restrict__ fc2_w,
    const float* __restrict__ fc2_b,
    float* __restrict__ out)
{
    extern __shared__ float sm[];
    float* sX   = sm;             // X tile / attention output
    float* sQ   = sm + ROW;       // Q / xr (proj output, residual)
    float* sK   = sm + 2 * ROW;   // K / layernorm output
    float* sV   = sm + 3 * ROW;   // V / gelu(fc1) chunk
    float* sRpb = sm + 4 * ROW;   // 507 floats

    const int tid  = threadIdx.x;
    const int warp = tid >> 5;
    const int lane = tid & 31;

    const int wid = blockIdx.x;
    const int b   = wid >> 10;
    const int wy  = (wid >> 5) & 31;
    const int wx  = wid & 31;
    const int hs0 = wy * WSZ;
    const int ws0 = wx * WSZ;

    // ---- relative position bias table to smem ----
    for (int i = tid; i < 507; i += 256) sRpb[i] = rpb[i];

    // ---- load window tile (shift is just a rolled index) ----
    for (int i = tid; i < NPAD * CDIM; i += 256) {
        int r = i / CDIM, c = i - r * CDIM;
        float v = 0.f;
        if (r < NTOK) {
            int ty = r / WSZ, tx = r - (r / WSZ) * WSZ;
            int h = hs0 + ty + SHIFT_SZ; if (h >= IMG) h -= IMG;
            int w = ws0 + tx + SHIFT_SZ; if (w >= IMG) w -= IMG;
            v = x[(((size_t)b * IMG + h) * IMG + w) * CDIM + c];
        }
        sX[r * PITCH + c] = v;
    }
    __syncthreads();

    const int n0 = warp * 7;   // this warp's 7 token rows

    // ================= Phase 2: QKV GEMM (56x288 = X @ qkv_w + b) =================
    for (int chunk = 0; chunk < 3; chunk++) {
        const int cb = chunk * 128 + lane * 4;
        if (cb < 288) {
            float acc[7][4];
            #pragma unroll
            for (int t = 0; t < 7; t++) {
                acc[t][0] = 0.f; acc[t][1] = 0.f; acc[t][2] = 0.f; acc[t][3] = 0.f;
            }
            const float* wp = qkv_w + cb;
            #pragma unroll 4
            for (int k = 0; k < CDIM; k++) {
                float4 w4 = *reinterpret_cast<const float4*>(wp + k * 288);
                #pragma unroll
                for (int t = 0; t < 7; t++) {
                    float xv = sX[(n0 + t) * PITCH + k];
                    acc[t][0] = fmaf(xv, w4.x, acc[t][0]);
                    acc[t][1] = fmaf(xv, w4.y, acc[t][1]);
                    acc[t][2] = fmaf(xv, w4.z, acc[t][2]);
                    acc[t][3] = fmaf(xv, w4.w, acc[t][3]);
                }
            }
            float4 b4 = *reinterpret_cast<const float4*>(qkv_b + cb);
            float bias[4] = {b4.x, b4.y, b4.z, b4.w};
            #pragma unroll
            for (int j = 0; j < 4; j++) {
                int c  = cb + j;
                int m  = c / CDIM;            // 0=q, 1=k, 2=v
                int cc = c - m * CDIM;        // = head*32 + d
                float* dst = (m == 0) ? sQ : (m == 1) ? sK : sV;
                float mul  = (m == 0) ? 0.17677669529663687f : 1.f; // 1/sqrt(32)
                #pragma unroll
                for (int t = 0; t < 7; t++)
                    dst[(n0 + t) * PITCH + cc] = (acc[t][j] + bias[j]) * mul;
            }
        }
    }
    __syncthreads();

    // ================= Phase 3: attention, one (head,row) per warp-task ==========
    for (int task = warp; task < NHEAD * NTOK; task += 8) {
        const int h    = task / NTOK;
        const int i    = task - h * NTOK;
        const int base = h * HDIM;
        const bool v2  = (lane < 17);
        const int j2   = v2 ? lane + 32 : lane;   // clamped safe row when invalid
        float s1 = 0.f, s2 = 0.f;
        const float* qr = sQ + i * PITCH + base;
        const float* k1 = sK + lane * PITCH + base;
        const float* k2 = sK + j2 * PITCH + base;
        #pragma unroll
        for (int d = 0; d < HDIM; d++) {
            float qd = qr[d];
            s1 = fmaf(qd, k1[d], s1);
            s2 = fmaf(qd, k2[d], s2);
        }
        const int yi = i / WSZ, xi = i - (i / WSZ) * WSZ;
        {
            int yj = lane / WSZ, xj = lane - (lane / WSZ) * WSZ;
            s1 += sRpb[((yi - yj + 6) * 13 + (xi - xj + 6)) * NHEAD + h];
        }
        if (v2) {
            int yj = j2 / WSZ, xj = j2 - (j2 / WSZ) * WSZ;
            s2 += sRpb[((yi - yj + 6) * 13 + (xi - xj + 6)) * NHEAD + h];
        } else {
            s2 = -1e30f;
        }
        float mx = fmaxf(s1, s2);
        #pragma unroll
        for (int o = 16; o > 0; o >>= 1)
            mx = fmaxf(mx, __shfl_xor_sync(0xffffffffu, mx, o));
        float e1 = __expf(s1 - mx);
        float e2 = v2 ? __expf(s2 - mx) : 0.f;
        float sum = e1 + e2;
        #pragma unroll
        for (int o = 16; o > 0; o >>= 1)
            sum += __shfl_xor_sync(0xffffffffu, sum, o);
        float inv = 1.f / sum;
        float p1 = e1 * inv, p2 = e2 * inv;

        float acc = 0.f;
        const float* vc = sV + base + lane;   // lane = output dim d
        #pragma unroll
        for (int j = 0; j < 32; j++) {
            float p = __shfl_sync(0xffffffffu, p1, j);
            acc = fmaf(p, vc[j * PITCH], acc);
        }
        #pragma unroll
        for (int j = 0; j < 17; j++) {
            float p = __shfl_sync(0xffffffffu, p2, j);
            acc = fmaf(p, vc[(j + 32) * PITCH], acc);
        }
        sX[i * PITCH + base + lane] = acc;    // attention output (head-major layout)
    }
    __syncthreads();
    // From here on every warp touches only its own 7 rows -> warp syncs suffice.

    const int  cb4 = lane * 4;
    const bool act = (lane < 24);   // 24 lanes x 4 cols cover the 96 channels

    // ================= Phase 4: output projection -> xr (into sQ) ================
    if (act) {
        float acc[7][4] = {};
        const float* wp = proj_w + cb4;
        #pragma unroll 4
        for (int k = 0; k < CDIM; k++) {
            float4 w4 = *reinterpret_cast<const float4*>(wp + k * CDIM);
            #pragma unroll
            for (int t = 0; t < 7; t++) {
                float av = sX[(n0 + t) * PITCH + k];
                acc[t][0] = fmaf(av, w4.x, acc[t][0]);
                acc[t][1] = fmaf(av, w4.y, acc[t][1]);
                acc[t][2] = fmaf(av, w4.z, acc[t][2]);
                acc[t][3] = fmaf(av, w4.w, acc[t][3]);
            }
        }
        float4 pb = *reinterpret_cast<const float4*>(proj_b + cb4);
        #pragma unroll
        for (int t = 0; t < 7; t++) {
            float* q = sQ + (n0 + t) * PITCH + cb4;
            q[0] = acc[t][0] + pb.x;
            q[1] = acc[t][1] + pb.y;
            q[2] = acc[t][2] + pb.z;
            q[3] = acc[t][3] + pb.w;
        }
    }
    __syncwarp();

    // ================= Phase 5: LayerNorm (xr -> sK) ==============================
    #pragma unroll
    for (int t = 0; t < 7; t++) {
        const float* row = sQ + (n0 + t) * PITCH;
        float v0 = row[lane], v1 = row[lane + 32], v2r = row[lane + 64];
        float s  = v0 + v1 + v2r;
        float sq = v0 * v0 + v1 * v1 + v2r * v2r;
        #pragma unroll
        for (int o = 16; o > 0; o >>= 1) {
            s  += __shfl_xor_sync(0xffffffffu, s, o);
            sq += __shfl_xor_sync(0xffffffffu, sq, o);
        }
        float mu   = s * (1.f / 96.f);
        float var  = sq * (1.f / 96.f) - mu * mu;
        float rstd = rsqrtf(var + 1e-5f);
        float* nr = sK + (n0 + t) * PITCH;
        nr[lane]      = (v0  - mu) * rstd * n2g[lane]      + n2b[lane];
        nr[lane + 32] = (v1  - mu) * rstd * n2g[lane + 32] + n2b[lane + 32];
        nr[lane + 64] = (v2r - mu) * rstd * n2g[lane + 64] + n2b[lane + 64];
    }
    __syncwarp();

    // ================= Phase 6: MLP, hidden chunked 4 x 96 ========================
    float oacc[7][4] = {};
    for (int chunk = 0; chunk < 4; chunk++) {
        const int hb = chunk * 96;
        if (act) {
            float acc[7][4] = {};
            const float* wp = fc1_w + hb + cb4;
            #pragma unroll 4
            for (int k = 0; k < CDIM; k++) {
                float4 w4 = *reinterpret_cast<const float4*>(wp + k * HID);
                #pragma unroll
                for (int t = 0; t < 7; t++) {
                    float nv = sK[(n0 + t) * PITCH + k];
                    acc[t][0] = fmaf(nv, w4.x, acc[t][0]);
                    acc[t][1] = fmaf(nv, w4.y, acc[t][1]);
                    acc[t][2] = fmaf(nv, w4.z, acc[t][2]);
                    acc[t][3] = fmaf(nv, w4.w, acc[t][3]);
                }
            }
            float4 b1 = *reinterpret_cast<const float4*>(fc1_b + hb + cb4);
            float bb[4] = {b1.x, b1.y, b1.z, b1.w};
            #pragma unroll
            for (int t = 0; t < 7; t++) {
                #pragma unroll
                for (int j = 0; j < 4; j++) {
                    float v = acc[t][j] + bb[j];
                    // exact gelu: x * 0.5 * (1 + erf(x / sqrt(2)))
                    float g = 0.5f * v * (1.f + erff(v * 0.70710678118654752f));
                    sV[(n0 + t) * PITCH + cb4 + j] = g;
                }
            }
        }
        __syncwarp();
        if (act) {
            const float* wp = fc2_w + (size_t)hb * CDIM + cb4;
            #pragma unroll 4
            for (int k = 0; k < CDIM; k++) {
                float4 w4 = *reinterpret_cast<const float4*>(wp + k * CDIM);
                #pragma unroll
                for (int t = 0; t < 7; t++) {
                    float hv = sV[(n0 + t) * PITCH + k];
                    oacc[t][0] = fmaf(hv, w4.x, oacc[t][0]);
                    oacc[t][1] = fmaf(hv, w4.y, oacc[t][1]);
                    oacc[t][2] = fmaf(hv, w4.z, oacc[t][2]);
                    oacc[t][3] = fmaf(hv, w4.w, oacc[t][3]);
                }
            }
        }
        __syncwarp();
    }

    // ================= Epilogue: residual + reverse shift + store =================
    if (act) {
        float4 b2 = *reinterpret_cast<const float4*>(fc2_b + cb4);
        #pragma unroll
        for (int t = 0; t < 7; t++) {
            int n = n0 + t;
            if (n < NTOK) {
                int ty = n / WSZ, tx = n - (n / WSZ) * WSZ;
                int h = hs0 + ty + SHIFT_SZ; if (h >= IMG) h -= IMG;
                int w = ws0 + tx + SHIFT_SZ; if (w >= IMG) w -= IMG;
                const float* res = sQ + n * PITCH + cb4;   // xr residual
                float4 o;
                o.x = res[0] + oacc[t][0] + b2.x;
                o.y = res[1] + oacc[t][1] + b2.y;
                o.z = res[2] + oacc[t][2] + b2.z;
                o.w = res[3] + oacc[t][3] + b2.w;
                *reinterpret_cast<float4*>(
                    out + (((size_t)b * IMG + h) * IMG + w) * CDIM + cb4) = o;
            }
        }
    }
}

} // namespace

extern "C" void kernel_launch(void* const* d_in, const int* in_sizes, int n_in,
                              void* d_out, int out_size) {
    (void)in_sizes; (void)n_in; (void)out_size;
    cudaFuncSetAttribute(swin_fused, cudaFuncAttributeMaxDynamicSharedMemorySize,
                         SMEM_BYTES);
    swin_fused<<<8 * 32 * 32, 256, SMEM_BYTES>>>(
        (const float*)d_in[0],  (const float*)d_in[1],  (const float*)d_in[2],
        (const float*)d_in[3],  (const float*)d_in[4],  (const float*)d_in[5],
        (const float*)d_in[6],  (const float*)d_in[7],  (const float*)d_in[8],
        (const float*)d_in[9],  (const float*)d_in[10], (const float*)d_in[11],
        (float*)d_out);
}